// round 2
// baseline (speedup 1.0000x reference)
#include <cuda_runtime.h>
#include <cuda_bf16.h>
#include <math.h>

// ---------------------------------------------------------------------------
// VisionModel: S=1280 tokens, D=1280, H=16 heads, HD=80, DEPTH=4
// Segments: tokens [0,1024) = seg0, [1024,1280) = seg1 (64-aligned)
// Output: (320, 1536) fp32
// ---------------------------------------------------------------------------

#define S_TOK 1280
#define DMODEL 1280
#define NHEAD 16
#define HDIM 80
#define DEPTH 4

// Scratch (device globals — no allocation allowed)
__device__ float g_x[S_TOK * DMODEL];        // residual stream
__device__ float g_ln[S_TOK * DMODEL];       // LN outputs (also merger input viewed (320,5120))
__device__ float g_qkv[S_TOK * 3 * DMODEL];  // qkv
__device__ float g_att[S_TOK * DMODEL];      // attention output
__device__ float g_big[S_TOK * 4 * DMODEL];  // fc1 out / m1 out

// ---------------------------------------------------------------------------
// GEMM: C[M,N] = A[M,K] @ B[N,K]^T + bias, with epilogue OP
// OP 0: none; 1: + resid; 2: SiLU gate t*sigmoid(1.702 t); 3: exact GELU
// BM=BN=128, BK=8, 256 threads, 8x8 per-thread tile.
// Requires: K % 8 == 0, N % 128 == 0 (M may be ragged).
// ---------------------------------------------------------------------------
template <int OP>
__global__ __launch_bounds__(256) void gemm128(
    const float* __restrict__ A, const float* __restrict__ B,
    const float* __restrict__ bias, const float* __restrict__ resid,
    float* __restrict__ C, int M, int N, int K)
{
    __shared__ float As[8][128];
    __shared__ float Bs[8][128];

    const int tid = threadIdx.x;
    const int tx = tid & 15;        // 0..15 -> N direction
    const int ty = tid >> 4;        // 0..15 -> M direction
    const int m0 = blockIdx.y * 128;
    const int n0 = blockIdx.x * 128;

    const int lrow = tid >> 1;          // 0..127
    const int lk   = (tid & 1) * 4;     // 0 or 4

    const bool arow_ok = (m0 + lrow) < M;
    const float* Aptr = A + (size_t)(m0 + lrow) * K + lk;
    const float* Bptr = B + (size_t)(n0 + lrow) * K + lk;

    float acc[8][8];
#pragma unroll
    for (int i = 0; i < 8; i++)
#pragma unroll
        for (int j = 0; j < 8; j++) acc[i][j] = 0.f;

    for (int k0 = 0; k0 < K; k0 += 8) {
        float4 av = arow_ok ? *(const float4*)(Aptr + k0) : make_float4(0.f, 0.f, 0.f, 0.f);
        float4 bv = *(const float4*)(Bptr + k0);
        As[lk + 0][lrow] = av.x; As[lk + 1][lrow] = av.y;
        As[lk + 2][lrow] = av.z; As[lk + 3][lrow] = av.w;
        Bs[lk + 0][lrow] = bv.x; Bs[lk + 1][lrow] = bv.y;
        Bs[lk + 2][lrow] = bv.z; Bs[lk + 3][lrow] = bv.w;
        __syncthreads();

#pragma unroll
        for (int kk = 0; kk < 8; kk++) {
            float4 a0 = *(const float4*)&As[kk][ty * 8];
            float4 a1 = *(const float4*)&As[kk][ty * 8 + 4];
            float4 b0 = *(const float4*)&Bs[kk][tx * 8];
            float4 b1 = *(const float4*)&Bs[kk][tx * 8 + 4];
            float af[8] = {a0.x, a0.y, a0.z, a0.w, a1.x, a1.y, a1.z, a1.w};
            float bf[8] = {b0.x, b0.y, b0.z, b0.w, b1.x, b1.y, b1.z, b1.w};
#pragma unroll
            for (int i = 0; i < 8; i++)
#pragma unroll
                for (int j = 0; j < 8; j++) acc[i][j] = fmaf(af[i], bf[j], acc[i][j]);
        }
        __syncthreads();
    }

    // epilogue
    float bv8[8];
#pragma unroll
    for (int j = 0; j < 8; j++) bv8[j] = bias ? bias[n0 + tx * 8 + j] : 0.f;

#pragma unroll
    for (int i = 0; i < 8; i++) {
        int m = m0 + ty * 8 + i;
        if (m >= M) continue;
#pragma unroll
        for (int j = 0; j < 8; j++) {
            int n = n0 + tx * 8 + j;
            float t = acc[i][j] + bv8[j];
            float v;
            if (OP == 0) {
                v = t;
            } else if (OP == 1) {
                v = t + resid[(size_t)m * N + n];
            } else if (OP == 2) {
                v = t / (1.f + __expf(-1.702f * t));
            } else { // OP == 3 exact GELU
                v = 0.5f * t * (1.f + erff(t * 0.7071067811865475f));
            }
            C[(size_t)m * N + n] = v;
        }
    }
}

// ---------------------------------------------------------------------------
// LayerNorm: one block per row of 1280
// ---------------------------------------------------------------------------
__global__ __launch_bounds__(256) void ln_kernel(
    const float* __restrict__ x, const float* __restrict__ w,
    const float* __restrict__ b, float* __restrict__ y)
{
    const int row = blockIdx.x;
    const int tid = threadIdx.x;
    const float* xr = x + (size_t)row * DMODEL;

    float s = 0.f, sq = 0.f;
#pragma unroll
    for (int i = 0; i < DMODEL / 256; i++) {
        float v = xr[tid + i * 256];
        s += v; sq += v * v;
    }
    // warp reduce
#pragma unroll
    for (int o = 16; o > 0; o >>= 1) {
        s  += __shfl_xor_sync(0xffffffffu, s, o);
        sq += __shfl_xor_sync(0xffffffffu, sq, o);
    }
    __shared__ float ws[8], wsq[8];
    if ((tid & 31) == 0) { ws[tid >> 5] = s; wsq[tid >> 5] = sq; }
    __syncthreads();
    __shared__ float s_mu, s_rstd;
    if (tid == 0) {
        float ts = 0.f, tsq = 0.f;
        for (int i = 0; i < 8; i++) { ts += ws[i]; tsq += wsq[i]; }
        float mu = ts / DMODEL;
        float var = tsq / DMODEL - mu * mu;
        s_mu = mu;
        s_rstd = rsqrtf(var + 1e-6f);
    }
    __syncthreads();
    float mu = s_mu, rstd = s_rstd;
    float* yr = y + (size_t)row * DMODEL;
#pragma unroll
    for (int i = 0; i < DMODEL / 256; i++) {
        int c = tid + i * 256;
        yr[c] = (xr[c] - mu) * rstd * w[c] + b[c];
    }
}

// ---------------------------------------------------------------------------
// RoPE: applied in place to q and k parts of g_qkv.
// Each thread handles the pair (d, d+40) of one (s, part, head).
// total threads = S * 2 * H * 40
// ---------------------------------------------------------------------------
__global__ void rope_kernel(float* __restrict__ qkv, const float* __restrict__ rotary)
{
    int i = blockIdx.x * blockDim.x + threadIdx.x;
    const int total = S_TOK * 2 * NHEAD * 40;
    if (i >= total) return;
    int d = i % 40;
    int h = (i / 40) % NHEAD;
    int part = (i / (40 * NHEAD)) % 2;
    int s = i / (40 * NHEAD * 2);

    int col = part * DMODEL + h * HDIM + d;
    float* base = qkv + (size_t)s * (3 * DMODEL);
    float x1 = base[col];
    float x2 = base[col + 40];
    float ang = rotary[s * 40 + d];
    float c, sn;
    sincosf(ang, &sn, &c);
    base[col]      = x1 * c - x2 * sn;
    base[col + 40] = x2 * c + x1 * sn;
}

// ---------------------------------------------------------------------------
// Attention (flash-style, block-diagonal segment mask by skipping chunks).
// grid: (NHEAD, S/64). block: 256 threads (16x16).
// Thread (tx,ty): queries q = ty*4 + i (i<4), dims dchunk = tx*5 + j (j<5).
// K/V key chunks of 64; segments are 64-aligned so a chunk is in or out.
// ---------------------------------------------------------------------------
#define ATT_SMEM_FLOATS (64 * 80 + 64 * 81 + 64 * 80 + 64 * 65 + 3 * 64)

__global__ __launch_bounds__(256) void attn_kernel(
    const float* __restrict__ qkv, const int* __restrict__ seg,
    float* __restrict__ out)
{
    extern __shared__ float sm[];
    float* Qs   = sm;                 // [64][80]
    float* Ks   = Qs + 64 * 80;       // [64][81] (pad to avoid bank conflicts)
    float* Vs   = Ks + 64 * 81;       // [64][80]
    float* Ss   = Vs + 64 * 80;       // [64][65]
    float* mrow = Ss + 64 * 65;       // [64]
    float* lrow = mrow + 64;          // [64]
    float* crow = lrow + 64;          // [64]

    const int head = blockIdx.x;
    const int q0   = blockIdx.y * 64;
    const int tid  = threadIdx.x;
    const int tx   = tid & 15;
    const int ty   = tid >> 4;

    const float scale = 0.11180339887498949f; // 1/sqrt(80)

    // load Q (scaled)
    for (int idx = tid; idx < 64 * 80; idx += 256) {
        int q = idx / 80, d = idx % 80;
        Qs[q * 80 + d] = qkv[(size_t)(q0 + q) * (3 * DMODEL) + head * HDIM + d] * scale;
    }
    if (tid < 64) { mrow[tid] = -1e30f; lrow[tid] = 0.f; }

    float acc[4][5];
#pragma unroll
    for (int i = 0; i < 4; i++)
#pragma unroll
        for (int j = 0; j < 5; j++) acc[i][j] = 0.f;

    const int myseg = seg[q0];
    __syncthreads();

    for (int c0 = 0; c0 < S_TOK; c0 += 64) {
        if (seg[c0] != myseg) continue;

        // load K, V chunk
        for (int idx = tid; idx < 64 * 80; idx += 256) {
            int k = idx / 80, d = idx % 80;
            size_t base = (size_t)(c0 + k) * (3 * DMODEL) + head * HDIM + d;
            Ks[k * 81 + d] = qkv[base + DMODEL];
            Vs[k * 80 + d] = qkv[base + 2 * DMODEL];
        }
        __syncthreads();

        // scores: thread computes S[ty*4+i][j*16+tx], i<4, j<4
        {
            float sc[4][4];
#pragma unroll
            for (int i = 0; i < 4; i++)
#pragma unroll
                for (int j = 0; j < 4; j++) sc[i][j] = 0.f;
            for (int d = 0; d < 80; d++) {
                float qa[4], kb[4];
#pragma unroll
                for (int i = 0; i < 4; i++) qa[i] = Qs[(ty * 4 + i) * 80 + d];
#pragma unroll
                for (int j = 0; j < 4; j++) kb[j] = Ks[(j * 16 + tx) * 81 + d];
#pragma unroll
                for (int i = 0; i < 4; i++)
#pragma unroll
                    for (int j = 0; j < 4; j++) sc[i][j] = fmaf(qa[i], kb[j], sc[i][j]);
            }
#pragma unroll
            for (int i = 0; i < 4; i++)
#pragma unroll
                for (int j = 0; j < 4; j++)
                    Ss[(ty * 4 + i) * 65 + (j * 16 + tx)] = sc[i][j];
        }
        __syncthreads();

        // online softmax row update: 4 threads per row
        {
            int r = tid >> 2, sub = tid & 3;
            float cmax = -1e30f;
            for (int c = sub * 16; c < sub * 16 + 16; c++)
                cmax = fmaxf(cmax, Ss[r * 65 + c]);
            cmax = fmaxf(cmax, __shfl_xor_sync(0xffffffffu, cmax, 1));
            cmax = fmaxf(cmax, __shfl_xor_sync(0xffffffffu, cmax, 2));
            float nm = fmaxf(mrow[r], cmax);
            float psum = 0.f;
            for (int c = sub * 16; c < sub * 16 + 16; c++) {
                float p = __expf(Ss[r * 65 + c] - nm);
                Ss[r * 65 + c] = p;
                psum += p;
            }
            psum += __shfl_xor_sync(0xffffffffu, psum, 1);
            psum += __shfl_xor_sync(0xffffffffu, psum, 2);
            if (sub == 0) {
                float cr = __expf(mrow[r] - nm);
                crow[r] = cr;
                lrow[r] = lrow[r] * cr + psum;
                mrow[r] = nm;
            }
        }
        __syncthreads();

        // rescale acc and accumulate P @ V
#pragma unroll
        for (int i = 0; i < 4; i++) {
            float cr = crow[ty * 4 + i];
#pragma unroll
            for (int j = 0; j < 5; j++) acc[i][j] *= cr;
        }
        for (int k = 0; k < 64; k++) {
            float p[4], vv[5];
#pragma unroll
            for (int i = 0; i < 4; i++) p[i] = Ss[(ty * 4 + i) * 65 + k];
#pragma unroll
            for (int j = 0; j < 5; j++) vv[j] = Vs[k * 80 + tx * 5 + j];
#pragma unroll
            for (int i = 0; i < 4; i++)
#pragma unroll
                for (int j = 0; j < 5; j++) acc[i][j] = fmaf(p[i], vv[j], acc[i][j]);
        }
        __syncthreads();
    }

    // write out
#pragma unroll
    for (int i = 0; i < 4; i++) {
        int q = ty * 4 + i;
        float inv = 1.f / lrow[q];
#pragma unroll
        for (int j = 0; j < 5; j++) {
            out[(size_t)(q0 + q) * DMODEL + head * HDIM + tx * 5 + j] = acc[i][j] * inv;
        }
    }
}

// ---------------------------------------------------------------------------
// Host side
// ---------------------------------------------------------------------------
static inline void run_gemm(int op, const float* A, const float* B,
                            const float* bias, const float* resid,
                            float* C, int M, int N, int K)
{
    dim3 grid(N / 128, (M + 127) / 128);
    switch (op) {
        case 0: gemm128<0><<<grid, 256>>>(A, B, bias, resid, C, M, N, K); break;
        case 1: gemm128<1><<<grid, 256>>>(A, B, bias, resid, C, M, N, K); break;
        case 2: gemm128<2><<<grid, 256>>>(A, B, bias, resid, C, M, N, K); break;
        case 3: gemm128<3><<<grid, 256>>>(A, B, bias, resid, C, M, N, K); break;
    }
}

extern "C" void kernel_launch(void* const* d_in, const int* in_sizes, int n_in,
                              void* d_out, int out_size)
{
    const float* pixels  = (const float*)d_in[0];   // (1280, 1176)
    const float* rotary  = (const float*)d_in[1];   // (1280, 40)
    const int*   seg_ids = (const int*)d_in[2];     // (1280,)
    const float* proj_w  = (const float*)d_in[3];   // (1280, 1176)
    const float* ln1_w   = (const float*)d_in[4];   // (4, 1280)
    const float* ln1_b   = (const float*)d_in[5];
    const float* qkv_w   = (const float*)d_in[6];   // (4, 3840, 1280)
    const float* qkv_b   = (const float*)d_in[7];   // (4, 3840)
    const float* po_w    = (const float*)d_in[8];   // (4, 1280, 1280)
    const float* po_b    = (const float*)d_in[9];
    const float* ln2_w   = (const float*)d_in[10];
    const float* ln2_b   = (const float*)d_in[11];
    const float* fc1_w   = (const float*)d_in[12];  // (4, 5120, 1280)
    const float* fc1_b   = (const float*)d_in[13];
    const float* fc2_w   = (const float*)d_in[14];  // (4, 1280, 5120)
    const float* fc2_b   = (const float*)d_in[15];
    const float* mln_w   = (const float*)d_in[16];
    const float* mln_b   = (const float*)d_in[17];
    const float* m1_w    = (const float*)d_in[18];  // (5120, 5120)
    const float* m1_b    = (const float*)d_in[19];
    const float* m2_w    = (const float*)d_in[20];  // (1536, 5120)
    const float* m2_b    = (const float*)d_in[21];
    float* out = (float*)d_out;                     // (320, 1536)

    float *x, *ln, *qkv, *att, *big;
    cudaGetSymbolAddress((void**)&x,   g_x);
    cudaGetSymbolAddress((void**)&ln,  g_ln);
    cudaGetSymbolAddress((void**)&qkv, g_qkv);
    cudaGetSymbolAddress((void**)&att, g_att);
    cudaGetSymbolAddress((void**)&big, g_big);

    cudaFuncSetAttribute(attn_kernel, cudaFuncAttributeMaxDynamicSharedMemorySize,
                         ATT_SMEM_FLOATS * (int)sizeof(float));

    // patch projection: x = pixels @ proj_w^T
    run_gemm(0, pixels, proj_w, nullptr, nullptr, x, S_TOK, DMODEL, 1176);

    for (int l = 0; l < DEPTH; l++) {
        // LN1
        ln_kernel<<<S_TOK, 256>>>(x, ln1_w + l * DMODEL, ln1_b + l * DMODEL, ln);
        // QKV
        run_gemm(0, ln, qkv_w + (size_t)l * 3 * DMODEL * DMODEL,
                 qkv_b + (size_t)l * 3 * DMODEL, nullptr, qkv,
                 S_TOK, 3 * DMODEL, DMODEL);
        // RoPE on q,k
        {
            int total = S_TOK * 2 * NHEAD * 40;
            rope_kernel<<<(total + 255) / 256, 256>>>(qkv, rotary);
        }
        // Attention
        {
            dim3 grid(NHEAD, S_TOK / 64);
            attn_kernel<<<grid, 256, ATT_SMEM_FLOATS * sizeof(float)>>>(qkv, seg_ids, att);
        }
        // proj out + residual -> x
        run_gemm(1, att, po_w + (size_t)l * DMODEL * DMODEL,
                 po_b + (size_t)l * DMODEL, x, x, S_TOK, DMODEL, DMODEL);
        // LN2
        ln_kernel<<<S_TOK, 256>>>(x, ln2_w + l * DMODEL, ln2_b + l * DMODEL, ln);
        // FC1 + SiLU gate
        run_gemm(2, ln, fc1_w + (size_t)l * 4 * DMODEL * DMODEL,
                 fc1_b + (size_t)l * 4 * DMODEL, nullptr, big,
                 S_TOK, 4 * DMODEL, DMODEL);
        // FC2 + residual -> x
        run_gemm(1, big, fc2_w + (size_t)l * DMODEL * 4 * DMODEL,
                 fc2_b + (size_t)l * DMODEL, x, x, S_TOK, DMODEL, 4 * DMODEL);
    }

    // merger LN
    ln_kernel<<<S_TOK, 256>>>(x, mln_w, mln_b, ln);
    // m1: (320, 5120) @ (5120,5120)^T + GELU  (ln viewed as (320, 5120))
    run_gemm(3, ln, m1_w, m1_b, nullptr, big, S_TOK / 4, 4 * DMODEL, 4 * DMODEL);
    // m2: (320, 5120) @ (1536,5120)^T -> out
    run_gemm(0, big, m2_w, m2_b, nullptr, out, S_TOK / 4, 1536, 4 * DMODEL);
}

// round 3
// speedup vs baseline: 2.1647x; 2.1647x over previous
#include <cuda_runtime.h>
#include <cuda_bf16.h>
#include <math.h>
#include <stdint.h>

// ---------------------------------------------------------------------------
// VisionModel: S=1280 tokens, D=1280, H=16 heads, HD=80, DEPTH=4
// Segments: tokens [0,1024) = seg0, [1024,1280) = seg1 (64-aligned)
// Output: (320, 1536) fp32
// ---------------------------------------------------------------------------

#define S_TOK 1280
#define DMODEL 1280
#define NHEAD 16
#define HDIM 80
#define DEPTH 4

// Scratch (device globals — no allocation allowed)
__device__ float g_x[S_TOK * DMODEL];
__device__ float g_ln[S_TOK * DMODEL];
__device__ float g_qkv[S_TOK * 3 * DMODEL];
__device__ float g_att[S_TOK * DMODEL];
__device__ float g_big[S_TOK * 4 * DMODEL];

// ===========================================================================
// tf32 tensor-core GEMM: C[M,N] = A[M,K] @ B[N,K]^T + bias, epilogue OP
// OP 0: none; 1: +resid; 2: SiLU gate; 3: exact GELU
// BM=BN=128, BK=16, 256 threads = 8 warps, warp tile 32x64 (m16n8k8 atoms).
// Requires K % 16 == 0, N % 128 == 0. M may be ragged.
// smem layout: [row][k'] with k' = (k%4)*4 + k/4, then col ^= ((row>>1)&3)<<2.
// One lds.128 per fragment group covers BOTH k=8 steps of a BK=16 slab.
// ===========================================================================

__device__ __forceinline__ uint32_t f2tf32(float f) {
    uint32_t r;
    asm("cvt.rna.tf32.f32 %0, %1;" : "=r"(r) : "f"(f));
    return r;
}

__device__ __forceinline__ void mma_tf32(float* c,
    uint32_t a0, uint32_t a1, uint32_t a2, uint32_t a3,
    uint32_t b0, uint32_t b1)
{
    asm volatile(
        "mma.sync.aligned.m16n8k8.row.col.f32.tf32.tf32.f32 "
        "{%0,%1,%2,%3},{%4,%5,%6,%7},{%8,%9},{%0,%1,%2,%3};"
        : "+f"(c[0]), "+f"(c[1]), "+f"(c[2]), "+f"(c[3])
        : "r"(a0), "r"(a1), "r"(a2), "r"(a3), "r"(b0), "r"(b1));
}

template <int OP>
__device__ __forceinline__ float ep_op(float t, float r) {
    if (OP == 0) return t;
    else if (OP == 1) return t + r;
    else if (OP == 2) return t / (1.f + __expf(-1.702f * t));
    else return 0.5f * t * (1.f + erff(t * 0.7071067811865475f));
}

template <int OP>
__global__ __launch_bounds__(256) void gemm_tf32(
    const float* __restrict__ A, const float* __restrict__ B,
    const float* __restrict__ bias, const float* __restrict__ resid,
    float* __restrict__ C, int M, int N, int K)
{
    __shared__ uint32_t As[2][128 * 16];
    __shared__ uint32_t Bs[2][128 * 16];

    const int tid  = threadIdx.x;
    const int warp = tid >> 5;
    const int lane = tid & 31;
    const int g = lane >> 2;       // group id 0..7
    const int t = lane & 3;        // thread-in-group 0..3

    const int m0 = blockIdx.y * 128;
    const int n0 = blockIdx.x * 128;
    const int warp_m = (warp & 3) * 32;
    const int warp_n = (warp >> 2) * 64;

    // global load assignment: row = tid>>1 (0..127), k-offset = (tid&1)*8
    const int lrow = tid >> 1;
    const int lk8  = (tid & 1) * 8;
    const bool arow_ok = (m0 + lrow) < M;
    const float* Ag = A + (size_t)(m0 + lrow) * K + lk8;
    const float* Bg = B + (size_t)(n0 + lrow) * K + lk8;
    const int sts_base = lrow * 16;
    const int sts_sw   = ((lrow >> 1) & 3) << 2;

    float acc[2][8][4];
#pragma unroll
    for (int am = 0; am < 2; am++)
#pragma unroll
        for (int bn = 0; bn < 8; bn++)
#pragma unroll
            for (int i = 0; i < 4; i++) acc[am][bn][i] = 0.f;

    const float4 z4 = make_float4(0.f, 0.f, 0.f, 0.f);
    float4 av0, av1, bv0, bv1;

    // prefetch stage 0
    av0 = arow_ok ? *(const float4*)(Ag + 0) : z4;
    av1 = arow_ok ? *(const float4*)(Ag + 4) : z4;
    bv0 = *(const float4*)(Bg + 0);
    bv1 = *(const float4*)(Bg + 4);

    // STS with k-permutation: local k = lk8 + j (+4): col' = j*4 + (lk8+..)/4
    // for k = lk8 + 0..3:  k%4=j, k/4 = lk8/4     -> col = j*4 + lk8/4
    // for k = lk8 + 4..7:  k%4=j, k/4 = lk8/4 + 1 -> col = j*4 + lk8/4 + 1
    const int kq = lk8 >> 2;   // 0 or 2
    {
        uint32_t* Ab = As[0]; uint32_t* Bb = Bs[0];
        const float a0v[4] = {av0.x, av0.y, av0.z, av0.w};
        const float a1v[4] = {av1.x, av1.y, av1.z, av1.w};
        const float b0v[4] = {bv0.x, bv0.y, bv0.z, bv0.w};
        const float b1v[4] = {bv1.x, bv1.y, bv1.z, bv1.w};
#pragma unroll
        for (int j = 0; j < 4; j++) {
            Ab[sts_base + ((j * 4 + kq)     ^ sts_sw)] = f2tf32(a0v[j]);
            Ab[sts_base + ((j * 4 + kq + 1) ^ sts_sw)] = f2tf32(a1v[j]);
            Bb[sts_base + ((j * 4 + kq)     ^ sts_sw)] = f2tf32(b0v[j]);
            Bb[sts_base + ((j * 4 + kq + 1) ^ sts_sw)] = f2tf32(b1v[j]);
        }
    }
    __syncthreads();

    const int nstages = K >> 4;
    int buf = 0;

    // fragment smem addresses (constant per thread)
    int a_addr[2][2], b_addr[8];
#pragma unroll
    for (int am = 0; am < 2; am++) {
        int rlo = warp_m + am * 16 + g;
        int rhi = rlo + 8;
        a_addr[am][0] = rlo * 16 + ((t * 4) ^ (((rlo >> 1) & 3) << 2));
        a_addr[am][1] = rhi * 16 + ((t * 4) ^ (((rhi >> 1) & 3) << 2));
    }
#pragma unroll
    for (int bn = 0; bn < 8; bn++) {
        int rn = warp_n + bn * 8 + g;
        b_addr[bn] = rn * 16 + ((t * 4) ^ (((rn >> 1) & 3) << 2));
    }

    for (int s = 0; s < nstages; s++) {
        const bool has_next = (s + 1 < nstages);
        if (has_next) {
            int k0 = (s + 1) << 4;
            av0 = arow_ok ? *(const float4*)(Ag + k0)     : z4;
            av1 = arow_ok ? *(const float4*)(Ag + k0 + 4) : z4;
            bv0 = *(const float4*)(Bg + k0);
            bv1 = *(const float4*)(Bg + k0 + 4);
        }

        // compute from buf
        {
            const uint32_t* Ab = As[buf];
            const uint32_t* Bb = Bs[buf];
            uint4 af[2][2];
#pragma unroll
            for (int am = 0; am < 2; am++) {
                af[am][0] = *(const uint4*)&Ab[a_addr[am][0]];
                af[am][1] = *(const uint4*)&Ab[a_addr[am][1]];
            }
            uint4 bf[8];
#pragma unroll
            for (int bn = 0; bn < 8; bn++) bf[bn] = *(const uint4*)&Bb[b_addr[bn]];

#pragma unroll
            for (int am = 0; am < 2; am++)
#pragma unroll
                for (int bn = 0; bn < 8; bn++) {
                    // k-step 0 (k = 0..7 of slab)
                    mma_tf32(acc[am][bn],
                             af[am][0].x, af[am][1].x, af[am][0].y, af[am][1].y,
                             bf[bn].x, bf[bn].y);
                    // k-step 1 (k = 8..15 of slab)
                    mma_tf32(acc[am][bn],
                             af[am][0].z, af[am][1].z, af[am][0].w, af[am][1].w,
                             bf[bn].z, bf[bn].w);
                }
        }

        if (has_next) {
            uint32_t* Ab = As[buf ^ 1]; uint32_t* Bb = Bs[buf ^ 1];
            const float a0v[4] = {av0.x, av0.y, av0.z, av0.w};
            const float a1v[4] = {av1.x, av1.y, av1.z, av1.w};
            const float b0v[4] = {bv0.x, bv0.y, bv0.z, bv0.w};
            const float b1v[4] = {bv1.x, bv1.y, bv1.z, bv1.w};
#pragma unroll
            for (int j = 0; j < 4; j++) {
                Ab[sts_base + ((j * 4 + kq)     ^ sts_sw)] = f2tf32(a0v[j]);
                Ab[sts_base + ((j * 4 + kq + 1) ^ sts_sw)] = f2tf32(a1v[j]);
                Bb[sts_base + ((j * 4 + kq)     ^ sts_sw)] = f2tf32(b0v[j]);
                Bb[sts_base + ((j * 4 + kq + 1) ^ sts_sw)] = f2tf32(b1v[j]);
            }
        }
        __syncthreads();
        buf ^= 1;
    }

    // epilogue
#pragma unroll
    for (int am = 0; am < 2; am++) {
        const int r0 = m0 + warp_m + am * 16 + g;
        const int r1 = r0 + 8;
#pragma unroll
        for (int bn = 0; bn < 8; bn++) {
            const int col = n0 + warp_n + bn * 8 + t * 2;
            const float2 bb = *(const float2*)&bias[col];
            const float* cc = acc[am][bn];
            if (r0 < M) {
                float rx = 0.f, ry = 0.f;
                if (OP == 1) { const float2 rr = *(const float2*)&resid[(size_t)r0 * N + col]; rx = rr.x; ry = rr.y; }
                float2 o; o.x = ep_op<OP>(cc[0] + bb.x, rx); o.y = ep_op<OP>(cc[1] + bb.y, ry);
                *(float2*)&C[(size_t)r0 * N + col] = o;
            }
            if (r1 < M) {
                float rx = 0.f, ry = 0.f;
                if (OP == 1) { const float2 rr = *(const float2*)&resid[(size_t)r1 * N + col]; rx = rr.x; ry = rr.y; }
                float2 o; o.x = ep_op<OP>(cc[2] + bb.x, rx); o.y = ep_op<OP>(cc[3] + bb.y, ry);
                *(float2*)&C[(size_t)r1 * N + col] = o;
            }
        }
    }
}

// ---------------------------------------------------------------------------
// fp32 fallback GEMM (proj only: K=1176 not %16). C = A @ B^T (no bias/op).
// ---------------------------------------------------------------------------
__global__ __launch_bounds__(256) void gemm128_f32(
    const float* __restrict__ A, const float* __restrict__ B,
    float* __restrict__ C, int M, int N, int K)
{
    __shared__ float As[8][128];
    __shared__ float Bs[8][128];

    const int tid = threadIdx.x;
    const int tx = tid & 15;
    const int ty = tid >> 4;
    const int m0 = blockIdx.y * 128;
    const int n0 = blockIdx.x * 128;
    const int lrow = tid >> 1;
    const int lk   = (tid & 1) * 4;

    const bool arow_ok = (m0 + lrow) < M;
    const float* Aptr = A + (size_t)(m0 + lrow) * K + lk;
    const float* Bptr = B + (size_t)(n0 + lrow) * K + lk;

    float acc[8][8];
#pragma unroll
    for (int i = 0; i < 8; i++)
#pragma unroll
        for (int j = 0; j < 8; j++) acc[i][j] = 0.f;

    for (int k0 = 0; k0 < K; k0 += 8) {
        float4 av = arow_ok ? *(const float4*)(Aptr + k0) : make_float4(0.f, 0.f, 0.f, 0.f);
        float4 bv = *(const float4*)(Bptr + k0);
        As[lk + 0][lrow] = av.x; As[lk + 1][lrow] = av.y;
        As[lk + 2][lrow] = av.z; As[lk + 3][lrow] = av.w;
        Bs[lk + 0][lrow] = bv.x; Bs[lk + 1][lrow] = bv.y;
        Bs[lk + 2][lrow] = bv.z; Bs[lk + 3][lrow] = bv.w;
        __syncthreads();

#pragma unroll
        for (int kk = 0; kk < 8; kk++) {
            float4 a0 = *(const float4*)&As[kk][ty * 8];
            float4 a1 = *(const float4*)&As[kk][ty * 8 + 4];
            float4 b0 = *(const float4*)&Bs[kk][tx * 8];
            float4 b1 = *(const float4*)&Bs[kk][tx * 8 + 4];
            float af[8] = {a0.x, a0.y, a0.z, a0.w, a1.x, a1.y, a1.z, a1.w};
            float bf[8] = {b0.x, b0.y, b0.z, b0.w, b1.x, b1.y, b1.z, b1.w};
#pragma unroll
            for (int i = 0; i < 8; i++)
#pragma unroll
                for (int j = 0; j < 8; j++) acc[i][j] = fmaf(af[i], bf[j], acc[i][j]);
        }
        __syncthreads();
    }

#pragma unroll
    for (int i = 0; i < 8; i++) {
        int m = m0 + ty * 8 + i;
        if (m >= M) continue;
#pragma unroll
        for (int j = 0; j < 8; j++)
            C[(size_t)m * N + n0 + tx * 8 + j] = acc[i][j];
    }
}

// ---------------------------------------------------------------------------
// LayerNorm
// ---------------------------------------------------------------------------
__global__ __launch_bounds__(256) void ln_kernel(
    const float* __restrict__ x, const float* __restrict__ w,
    const float* __restrict__ b, float* __restrict__ y)
{
    const int row = blockIdx.x;
    const int tid = threadIdx.x;
    const float* xr = x + (size_t)row * DMODEL;

    float s = 0.f, sq = 0.f;
#pragma unroll
    for (int i = 0; i < DMODEL / 256; i++) {
        float v = xr[tid + i * 256];
        s += v; sq += v * v;
    }
#pragma unroll
    for (int o = 16; o > 0; o >>= 1) {
        s  += __shfl_xor_sync(0xffffffffu, s, o);
        sq += __shfl_xor_sync(0xffffffffu, sq, o);
    }
    __shared__ float ws[8], wsq[8];
    if ((tid & 31) == 0) { ws[tid >> 5] = s; wsq[tid >> 5] = sq; }
    __syncthreads();
    __shared__ float s_mu, s_rstd;
    if (tid == 0) {
        float ts = 0.f, tsq = 0.f;
        for (int i = 0; i < 8; i++) { ts += ws[i]; tsq += wsq[i]; }
        float mu = ts / DMODEL;
        float var = tsq / DMODEL - mu * mu;
        s_mu = mu;
        s_rstd = rsqrtf(var + 1e-6f);
    }
    __syncthreads();
    float mu = s_mu, rstd = s_rstd;
    float* yr = y + (size_t)row * DMODEL;
#pragma unroll
    for (int i = 0; i < DMODEL / 256; i++) {
        int c = tid + i * 256;
        yr[c] = (xr[c] - mu) * rstd * w[c] + b[c];
    }
}

// ---------------------------------------------------------------------------
// RoPE in place on q,k of g_qkv
// ---------------------------------------------------------------------------
__global__ void rope_kernel(float* __restrict__ qkv, const float* __restrict__ rotary)
{
    int i = blockIdx.x * blockDim.x + threadIdx.x;
    const int total = S_TOK * 2 * NHEAD * 40;
    if (i >= total) return;
    int d = i % 40;
    int h = (i / 40) % NHEAD;
    int part = (i / (40 * NHEAD)) % 2;
    int s = i / (40 * NHEAD * 2);

    int col = part * DMODEL + h * HDIM + d;
    float* base = qkv + (size_t)s * (3 * DMODEL);
    float x1 = base[col];
    float x2 = base[col + 40];
    float ang = rotary[s * 40 + d];
    float c, sn;
    sincosf(ang, &sn, &c);
    base[col]      = x1 * c - x2 * sn;
    base[col + 40] = x2 * c + x1 * sn;
}

// ---------------------------------------------------------------------------
// Attention (flash-style, segment mask via chunk skipping)
// ---------------------------------------------------------------------------
#define ATT_SMEM_FLOATS (64 * 80 + 64 * 81 + 64 * 80 + 64 * 65 + 3 * 64)

__global__ __launch_bounds__(256) void attn_kernel(
    const float* __restrict__ qkv, const int* __restrict__ seg,
    float* __restrict__ out)
{
    extern __shared__ float sm[];
    float* Qs   = sm;
    float* Ks   = Qs + 64 * 80;
    float* Vs   = Ks + 64 * 81;
    float* Ss   = Vs + 64 * 80;
    float* mrow = Ss + 64 * 65;
    float* lrow = mrow + 64;
    float* crow = lrow + 64;

    const int head = blockIdx.x;
    const int q0   = blockIdx.y * 64;
    const int tid  = threadIdx.x;
    const int tx   = tid & 15;
    const int ty   = tid >> 4;

    const float scale = 0.11180339887498949f;

    for (int idx = tid; idx < 64 * 80; idx += 256) {
        int q = idx / 80, d = idx % 80;
        Qs[q * 80 + d] = qkv[(size_t)(q0 + q) * (3 * DMODEL) + head * HDIM + d] * scale;
    }
    if (tid < 64) { mrow[tid] = -1e30f; lrow[tid] = 0.f; }

    float acc[4][5];
#pragma unroll
    for (int i = 0; i < 4; i++)
#pragma unroll
        for (int j = 0; j < 5; j++) acc[i][j] = 0.f;

    const int myseg = seg[q0];
    __syncthreads();

    for (int c0 = 0; c0 < S_TOK; c0 += 64) {
        if (seg[c0] != myseg) continue;

        for (int idx = tid; idx < 64 * 80; idx += 256) {
            int k = idx / 80, d = idx % 80;
            size_t base = (size_t)(c0 + k) * (3 * DMODEL) + head * HDIM + d;
            Ks[k * 81 + d] = qkv[base + DMODEL];
            Vs[k * 80 + d] = qkv[base + 2 * DMODEL];
        }
        __syncthreads();

        {
            float sc[4][4];
#pragma unroll
            for (int i = 0; i < 4; i++)
#pragma unroll
                for (int j = 0; j < 4; j++) sc[i][j] = 0.f;
            for (int d = 0; d < 80; d++) {
                float qa[4], kb[4];
#pragma unroll
                for (int i = 0; i < 4; i++) qa[i] = Qs[(ty * 4 + i) * 80 + d];
#pragma unroll
                for (int j = 0; j < 4; j++) kb[j] = Ks[(j * 16 + tx) * 81 + d];
#pragma unroll
                for (int i = 0; i < 4; i++)
#pragma unroll
                    for (int j = 0; j < 4; j++) sc[i][j] = fmaf(qa[i], kb[j], sc[i][j]);
            }
#pragma unroll
            for (int i = 0; i < 4; i++)
#pragma unroll
                for (int j = 0; j < 4; j++)
                    Ss[(ty * 4 + i) * 65 + (j * 16 + tx)] = sc[i][j];
        }
        __syncthreads();

        {
            int r = tid >> 2, sub = tid & 3;
            float cmax = -1e30f;
            for (int c = sub * 16; c < sub * 16 + 16; c++)
                cmax = fmaxf(cmax, Ss[r * 65 + c]);
            cmax = fmaxf(cmax, __shfl_xor_sync(0xffffffffu, cmax, 1));
            cmax = fmaxf(cmax, __shfl_xor_sync(0xffffffffu, cmax, 2));
            float nm = fmaxf(mrow[r], cmax);
            float psum = 0.f;
            for (int c = sub * 16; c < sub * 16 + 16; c++) {
                float p = __expf(Ss[r * 65 + c] - nm);
                Ss[r * 65 + c] = p;
                psum += p;
            }
            psum += __shfl_xor_sync(0xffffffffu, psum, 1);
            psum += __shfl_xor_sync(0xffffffffu, psum, 2);
            if (sub == 0) {
                float cr = __expf(mrow[r] - nm);
                crow[r] = cr;
                lrow[r] = lrow[r] * cr + psum;
                mrow[r] = nm;
            }
        }
        __syncthreads();

#pragma unroll
        for (int i = 0; i < 4; i++) {
            float cr = crow[ty * 4 + i];
#pragma unroll
            for (int j = 0; j < 5; j++) acc[i][j] *= cr;
        }
        for (int k = 0; k < 64; k++) {
            float p[4], vv[5];
#pragma unroll
            for (int i = 0; i < 4; i++) p[i] = Ss[(ty * 4 + i) * 65 + k];
#pragma unroll
            for (int j = 0; j < 5; j++) vv[j] = Vs[k * 80 + tx * 5 + j];
#pragma unroll
            for (int i = 0; i < 4; i++)
#pragma unroll
                for (int j = 0; j < 5; j++) acc[i][j] = fmaf(p[i], vv[j], acc[i][j]);
        }
        __syncthreads();
    }

#pragma unroll
    for (int i = 0; i < 4; i++) {
        int q = ty * 4 + i;
        float inv = 1.f / lrow[q];
#pragma unroll
        for (int j = 0; j < 5; j++) {
            out[(size_t)(q0 + q) * DMODEL + head * HDIM + tx * 5 + j] = acc[i][j] * inv;
        }
    }
}

// ---------------------------------------------------------------------------
// Host side
// ---------------------------------------------------------------------------
static inline void run_gemm_tc(int op, const float* A, const float* B,
                               const float* bias, const float* resid,
                               float* C, int M, int N, int K)
{
    dim3 grid(N / 128, (M + 127) / 128);
    switch (op) {
        case 0: gemm_tf32<0><<<grid, 256>>>(A, B, bias, resid, C, M, N, K); break;
        case 1: gemm_tf32<1><<<grid, 256>>>(A, B, bias, resid, C, M, N, K); break;
        case 2: gemm_tf32<2><<<grid, 256>>>(A, B, bias, resid, C, M, N, K); break;
        case 3: gemm_tf32<3><<<grid, 256>>>(A, B, bias, resid, C, M, N, K); break;
    }
}

extern "C" void kernel_launch(void* const* d_in, const int* in_sizes, int n_in,
                              void* d_out, int out_size)
{
    const float* pixels  = (const float*)d_in[0];
    const float* rotary  = (const float*)d_in[1];
    const int*   seg_ids = (const int*)d_in[2];
    const float* proj_w  = (const float*)d_in[3];
    const float* ln1_w   = (const float*)d_in[4];
    const float* ln1_b   = (const float*)d_in[5];
    const float* qkv_w   = (const float*)d_in[6];
    const float* qkv_b   = (const float*)d_in[7];
    const float* po_w    = (const float*)d_in[8];
    const float* po_b    = (const float*)d_in[9];
    const float* ln2_w   = (const float*)d_in[10];
    const float* ln2_b   = (const float*)d_in[11];
    const float* fc1_w   = (const float*)d_in[12];
    const float* fc1_b   = (const float*)d_in[13];
    const float* fc2_w   = (const float*)d_in[14];
    const float* fc2_b   = (const float*)d_in[15];
    const float* mln_w   = (const float*)d_in[16];
    const float* mln_b   = (const float*)d_in[17];
    const float* m1_w    = (const float*)d_in[18];
    const float* m1_b    = (const float*)d_in[19];
    const float* m2_w    = (const float*)d_in[20];
    const float* m2_b    = (const float*)d_in[21];
    float* out = (float*)d_out;

    float *x, *ln, *qkv, *att, *big;
    cudaGetSymbolAddress((void**)&x,   g_x);
    cudaGetSymbolAddress((void**)&ln,  g_ln);
    cudaGetSymbolAddress((void**)&qkv, g_qkv);
    cudaGetSymbolAddress((void**)&att, g_att);
    cudaGetSymbolAddress((void**)&big, g_big);

    cudaFuncSetAttribute(attn_kernel, cudaFuncAttributeMaxDynamicSharedMemorySize,
                         ATT_SMEM_FLOATS * (int)sizeof(float));

    // patch projection: x = pixels @ proj_w^T (K=1176 not %16 -> fp32 path)
    {
        dim3 grid(DMODEL / 128, S_TOK / 128);
        gemm128_f32<<<grid, 256>>>(pixels, proj_w, x, S_TOK, DMODEL, 1176);
    }

    for (int l = 0; l < DEPTH; l++) {
        ln_kernel<<<S_TOK, 256>>>(x, ln1_w + l * DMODEL, ln1_b + l * DMODEL, ln);
        run_gemm_tc(0, ln, qkv_w + (size_t)l * 3 * DMODEL * DMODEL,
                    qkv_b + (size_t)l * 3 * DMODEL, nullptr, qkv,
                    S_TOK, 3 * DMODEL, DMODEL);
        {
            int total = S_TOK * 2 * NHEAD * 40;
            rope_kernel<<<(total + 255) / 256, 256>>>(qkv, rotary);
        }
        {
            dim3 grid(NHEAD, S_TOK / 64);
            attn_kernel<<<grid, 256, ATT_SMEM_FLOATS * sizeof(float)>>>(qkv, seg_ids, att);
        }
        run_gemm_tc(1, att, po_w + (size_t)l * DMODEL * DMODEL,
                    po_b + (size_t)l * DMODEL, x, x, S_TOK, DMODEL, DMODEL);
        ln_kernel<<<S_TOK, 256>>>(x, ln2_w + l * DMODEL, ln2_b + l * DMODEL, ln);
        run_gemm_tc(2, ln, fc1_w + (size_t)l * 4 * DMODEL * DMODEL,
                    fc1_b + (size_t)l * 4 * DMODEL, nullptr, big,
                    S_TOK, 4 * DMODEL, DMODEL);
        run_gemm_tc(1, big, fc2_w + (size_t)l * DMODEL * 4 * DMODEL,
                    fc2_b + (size_t)l * DMODEL, x, x, S_TOK, DMODEL, 4 * DMODEL);
    }

    ln_kernel<<<S_TOK, 256>>>(x, mln_w, mln_b, ln);
    run_gemm_tc(3, ln, m1_w, m1_b, nullptr, big, S_TOK / 4, 4 * DMODEL, 4 * DMODEL);
    run_gemm_tc(0, big, m2_w, m2_b, nullptr, out, S_TOK / 4, 1536, 4 * DMODEL);
}

// round 5
// speedup vs baseline: 2.9195x; 1.3487x over previous
#include <cuda_runtime.h>
#include <cuda_bf16.h>
#include <math.h>
#include <stdint.h>

// ---------------------------------------------------------------------------
// VisionModel: S=1280, D=1280, H=16, HD=80, DEPTH=4. Output (320,1536) fp32.
// GEMMs: fp16 mma.sync m16n8k16 (fp32 accum). Attention/LN/rope fp32.
// (tcgen05 unavailable: harness ptxas targets compute_103 base.)
// ---------------------------------------------------------------------------

#define S_TOK 1280
#define DMODEL 1280
#define NHEAD 16
#define HDIM 80
#define DEPTH 4

__device__ float g_x[S_TOK * DMODEL];
__device__ float g_ln[S_TOK * DMODEL];
__device__ float g_qkv[S_TOK * 3 * DMODEL];   // also m2 split-K partials (4*320*1536 fits)
__device__ float g_att[S_TOK * DMODEL];
__device__ float g_big[S_TOK * 4 * DMODEL];

// ===========================================================================
// fp16 GEMM: C[M,N] = A[M,K] @ B[N,K]^T + bias, epilogue OP
// OP 0: none; 1: +resid; 2: SiLU gate; 3: exact GELU; 4: split-K partial
//       (OP 4: koff = blockIdx.z*K applied to A,B cols; C += z*M*N; no bias)
// BM=BN=128, BK=16, 256 threads = 8 warps, warp tile 32x64 (m16n8k16 atoms).
// smem: fp16 pairs, pair-col permutation c=(k2&3)*2+(k2>>2), row swizzle
// col ^= ((r^(r>>2))&3)<<1  -> conflict-free STS.32 / LDS.64.
// Requires N % 128 == 0, K % 8 == 0. M ragged OK.
// ===========================================================================

__device__ __forceinline__ uint32_t pack_f16(float lo, float hi) {
    uint32_t r;
    asm("cvt.rn.f16x2.f32 %0, %1, %2;" : "=r"(r) : "f"(hi), "f"(lo));
    return r;
}

__device__ __forceinline__ void mma_f16(float* c,
    uint32_t a0, uint32_t a1, uint32_t a2, uint32_t a3,
    uint32_t b0, uint32_t b1)
{
    asm volatile(
        "mma.sync.aligned.m16n8k16.row.col.f32.f16.f16.f32 "
        "{%0,%1,%2,%3},{%4,%5,%6,%7},{%8,%9},{%0,%1,%2,%3};"
        : "+f"(c[0]), "+f"(c[1]), "+f"(c[2]), "+f"(c[3])
        : "r"(a0), "r"(a1), "r"(a2), "r"(a3), "r"(b0), "r"(b1));
}

template <int OP>
__device__ __forceinline__ float ep_op(float t, float r) {
    if (OP == 0 || OP == 4) return t;
    else if (OP == 1) return t + r;
    else if (OP == 2) return t / (1.f + __expf(-1.702f * t));
    else return 0.5f * t * (1.f + erff(t * 0.7071067811865475f));
}

__device__ __forceinline__ int swz(int r) { return ((r ^ (r >> 2)) & 3) << 1; }

template <int OP>
__global__ __launch_bounds__(256) void gemm_f16(
    const float* __restrict__ A, int lda,
    const float* __restrict__ B, int ldb,
    const float* __restrict__ bias, const float* __restrict__ resid,
    float* __restrict__ C, int M, int N, int K)
{
    // [row 0..127][pair-col 0..7] per buffer
    __shared__ uint32_t As[2][128 * 8];
    __shared__ uint32_t Bs[2][128 * 8];

    if (OP == 4) {
        const size_t zo = (size_t)blockIdx.z * K;
        A += zo; B += zo;
        C += (size_t)blockIdx.z * (size_t)M * N;
    }

    const int tid  = threadIdx.x;
    const int warp = tid >> 5;
    const int lane = tid & 31;
    const int g = lane >> 2;
    const int t = lane & 3;

    const int m0 = blockIdx.y * 128;
    const int n0 = blockIdx.x * 128;
    const int warp_m = (warp & 3) * 32;
    const int warp_n = (warp >> 2) * 64;

    // producer: row = tid>>1 (0..127), k-half = (tid&1)*8
    const int prow  = tid >> 1;
    const int khalf = tid & 1;
    const int pk8   = khalf * 8;
    const bool arow_ok = (m0 + prow) < M;
    const float* Ag = A + (size_t)(m0 + prow) * lda + pk8;
    const float* Bg = B + (size_t)(n0 + prow) * ldb + pk8;
    const int psw = swz(prow);
    int pcol[4];
#pragma unroll
    for (int j = 0; j < 4; j++) pcol[j] = prow * 8 + ((j * 2 + khalf) ^ psw);

    float acc[2][8][4];
#pragma unroll
    for (int am = 0; am < 2; am++)
#pragma unroll
        for (int bn = 0; bn < 8; bn++)
#pragma unroll
            for (int i = 0; i < 4; i++) acc[am][bn][i] = 0.f;

    const float4 z4 = make_float4(0.f, 0.f, 0.f, 0.f);
    float4 av0, av1, bv0, bv1;

    // stage-0 load
    av0 = (arow_ok && pk8 < K)     ? *(const float4*)(Ag + 0) : z4;
    av1 = (arow_ok && pk8 + 4 < K) ? *(const float4*)(Ag + 4) : z4;
    bv0 = (pk8 < K)     ? *(const float4*)(Bg + 0) : z4;
    bv1 = (pk8 + 4 < K) ? *(const float4*)(Bg + 4) : z4;
    {
        const float a[8] = {av0.x, av0.y, av0.z, av0.w, av1.x, av1.y, av1.z, av1.w};
        const float b[8] = {bv0.x, bv0.y, bv0.z, bv0.w, bv1.x, bv1.y, bv1.z, bv1.w};
#pragma unroll
        for (int j = 0; j < 4; j++) {
            As[0][pcol[j]] = pack_f16(a[2 * j], a[2 * j + 1]);
            Bs[0][pcol[j]] = pack_f16(b[2 * j], b[2 * j + 1]);
        }
    }
    __syncthreads();

    // fragment element offsets (uint32 units), constant per thread
    int aoff[2][2], boff[8];
#pragma unroll
    for (int am = 0; am < 2; am++) {
        const int rl = warp_m + am * 16 + g;
        const int rh = rl + 8;
        aoff[am][0] = rl * 8 + ((2 * t) ^ swz(rl));
        aoff[am][1] = rh * 8 + ((2 * t) ^ swz(rh));
    }
#pragma unroll
    for (int bn = 0; bn < 8; bn++) {
        const int rn = warp_n + bn * 8 + g;
        boff[bn] = rn * 8 + ((2 * t) ^ swz(rn));
    }

    const int nstages = (K + 15) >> 4;
    int buf = 0;

    for (int s = 0; s < nstages; s++) {
        const bool has_next = (s + 1 < nstages);
        if (has_next) {
            const int k0 = (s + 1) << 4;
            av0 = (arow_ok && k0 + pk8 < K)     ? *(const float4*)(Ag + k0)     : z4;
            av1 = (arow_ok && k0 + pk8 + 4 < K) ? *(const float4*)(Ag + k0 + 4) : z4;
            bv0 = (k0 + pk8 < K)     ? *(const float4*)(Bg + k0)     : z4;
            bv1 = (k0 + pk8 + 4 < K) ? *(const float4*)(Bg + k0 + 4) : z4;
        }

        // compute from buf
        {
            const uint32_t* Ab = As[buf];
            const uint32_t* Bb = Bs[buf];
            uint2 afl[2], afh[2];
#pragma unroll
            for (int am = 0; am < 2; am++) {
                afl[am] = *(const uint2*)&Ab[aoff[am][0]];   // row g:  {k-lo, k-hi}
                afh[am] = *(const uint2*)&Ab[aoff[am][1]];   // row g+8
            }
            uint2 bf[8];
#pragma unroll
            for (int bn = 0; bn < 8; bn++) bf[bn] = *(const uint2*)&Bb[boff[bn]];

#pragma unroll
            for (int am = 0; am < 2; am++)
#pragma unroll
                for (int bn = 0; bn < 8; bn++)
                    mma_f16(acc[am][bn],
                            afl[am].x, afh[am].x, afl[am].y, afh[am].y,
                            bf[bn].x, bf[bn].y);
        }

        if (has_next) {
            const float a[8] = {av0.x, av0.y, av0.z, av0.w, av1.x, av1.y, av1.z, av1.w};
            const float b[8] = {bv0.x, bv0.y, bv0.z, bv0.w, bv1.x, bv1.y, bv1.z, bv1.w};
            uint32_t* Ab = As[buf ^ 1];
            uint32_t* Bb = Bs[buf ^ 1];
#pragma unroll
            for (int j = 0; j < 4; j++) {
                Ab[pcol[j]] = pack_f16(a[2 * j], a[2 * j + 1]);
                Bb[pcol[j]] = pack_f16(b[2 * j], b[2 * j + 1]);
            }
        }
        __syncthreads();
        buf ^= 1;
    }

    // epilogue
#pragma unroll
    for (int am = 0; am < 2; am++) {
        const int r0 = m0 + warp_m + am * 16 + g;
        const int r1 = r0 + 8;
#pragma unroll
        for (int bn = 0; bn < 8; bn++) {
            const int col = n0 + warp_n + bn * 8 + t * 2;
            const float2 bb = bias ? *(const float2*)&bias[col]
                                   : make_float2(0.f, 0.f);
            const float* cc = acc[am][bn];
            if (r0 < M) {
                float rx = 0.f, ry = 0.f;
                if (OP == 1) { const float2 rr = *(const float2*)&resid[(size_t)r0 * N + col]; rx = rr.x; ry = rr.y; }
                float2 o; o.x = ep_op<OP>(cc[0] + bb.x, rx); o.y = ep_op<OP>(cc[1] + bb.y, ry);
                *(float2*)&C[(size_t)r0 * N + col] = o;
            }
            if (r1 < M) {
                float rx = 0.f, ry = 0.f;
                if (OP == 1) { const float2 rr = *(const float2*)&resid[(size_t)r1 * N + col]; rx = rr.x; ry = rr.y; }
                float2 o; o.x = ep_op<OP>(cc[2] + bb.x, rx); o.y = ep_op<OP>(cc[3] + bb.y, ry);
                *(float2*)&C[(size_t)r1 * N + col] = o;
            }
        }
    }
}

// m2 split-K reduce: out[320,1536] = sum of 4 partials + bias
__global__ void reduce_m2(const float* __restrict__ part,
                          const float* __restrict__ bias,
                          float* __restrict__ out)
{
    const int i = blockIdx.x * 256 + threadIdx.x;
    const int total = 320 * 1536;
    if (i >= total) return;
    float s = bias[i % 1536];
#pragma unroll
    for (int c = 0; c < 4; c++) s += part[(size_t)c * total + i];
    out[i] = s;
}

// ---------------------------------------------------------------------------
// LayerNorm
// ---------------------------------------------------------------------------
__global__ __launch_bounds__(256) void ln_kernel(
    const float* __restrict__ x, const float* __restrict__ w,
    const float* __restrict__ b, float* __restrict__ y)
{
    const int row = blockIdx.x;
    const int tid = threadIdx.x;
    const float* xr = x + (size_t)row * DMODEL;

    float s = 0.f, sq = 0.f;
#pragma unroll
    for (int i = 0; i < DMODEL / 256; i++) {
        float v = xr[tid + i * 256];
        s += v; sq += v * v;
    }
#pragma unroll
    for (int o = 16; o > 0; o >>= 1) {
        s  += __shfl_xor_sync(0xffffffffu, s, o);
        sq += __shfl_xor_sync(0xffffffffu, sq, o);
    }
    __shared__ float ws[8], wsq[8];
    if ((tid & 31) == 0) { ws[tid >> 5] = s; wsq[tid >> 5] = sq; }
    __syncthreads();
    __shared__ float s_mu, s_rstd;
    if (tid == 0) {
        float ts = 0.f, tsq = 0.f;
        for (int i = 0; i < 8; i++) { ts += ws[i]; tsq += wsq[i]; }
        float mu = ts / DMODEL;
        float var = tsq / DMODEL - mu * mu;
        s_mu = mu;
        s_rstd = rsqrtf(var + 1e-6f);
    }
    __syncthreads();
    float mu = s_mu, rstd = s_rstd;
    float* yr = y + (size_t)row * DMODEL;
#pragma unroll
    for (int i = 0; i < DMODEL / 256; i++) {
        int c = tid + i * 256;
        yr[c] = (xr[c] - mu) * rstd * w[c] + b[c];
    }
}

// ---------------------------------------------------------------------------
// RoPE in place on q,k of g_qkv
// ---------------------------------------------------------------------------
__global__ void rope_kernel(float* __restrict__ qkv, const float* __restrict__ rotary)
{
    int i = blockIdx.x * blockDim.x + threadIdx.x;
    const int total = S_TOK * 2 * NHEAD * 40;
    if (i >= total) return;
    int d = i % 40;
    int h = (i / 40) % NHEAD;
    int part = (i / (40 * NHEAD)) % 2;
    int s = i / (40 * NHEAD * 2);

    int col = part * DMODEL + h * HDIM + d;
    float* base = qkv + (size_t)s * (3 * DMODEL);
    float x1 = base[col];
    float x2 = base[col + 40];
    float ang = rotary[s * 40 + d];
    float c, sn;
    sincosf(ang, &sn, &c);
    base[col]      = x1 * c - x2 * sn;
    base[col + 40] = x2 * c + x1 * sn;
}

// ---------------------------------------------------------------------------
// Attention (flash-style fp32, segment mask via chunk skipping)
// ---------------------------------------------------------------------------
#define ATT_SMEM_FLOATS (64 * 80 + 64 * 81 + 64 * 80 + 64 * 65 + 3 * 64)

__global__ __launch_bounds__(256) void attn_kernel(
    const float* __restrict__ qkv, const int* __restrict__ seg,
    float* __restrict__ out)
{
    extern __shared__ float sm[];
    float* Qs   = sm;
    float* Ks   = Qs + 64 * 80;
    float* Vs   = Ks + 64 * 81;
    float* Ss   = Vs + 64 * 80;
    float* mrow = Ss + 64 * 65;
    float* lrow = mrow + 64;
    float* crow = lrow + 64;

    const int head = blockIdx.x;
    const int q0   = blockIdx.y * 64;
    const int tid  = threadIdx.x;
    const int tx   = tid & 15;
    const int ty   = tid >> 4;

    const float scale = 0.11180339887498949f;

    for (int idx = tid; idx < 64 * 80; idx += 256) {
        int q = idx / 80, d = idx % 80;
        Qs[q * 80 + d] = qkv[(size_t)(q0 + q) * (3 * DMODEL) + head * HDIM + d] * scale;
    }
    if (tid < 64) { mrow[tid] = -1e30f; lrow[tid] = 0.f; }

    float acc[4][5];
#pragma unroll
    for (int i = 0; i < 4; i++)
#pragma unroll
        for (int j = 0; j < 5; j++) acc[i][j] = 0.f;

    const int myseg = seg[q0];
    __syncthreads();

    for (int c0 = 0; c0 < S_TOK; c0 += 64) {
        if (seg[c0] != myseg) continue;

        for (int idx = tid; idx < 64 * 80; idx += 256) {
            int k = idx / 80, d = idx % 80;
            size_t base = (size_t)(c0 + k) * (3 * DMODEL) + head * HDIM + d;
            Ks[k * 81 + d] = qkv[base + DMODEL];
            Vs[k * 80 + d] = qkv[base + 2 * DMODEL];
        }
        __syncthreads();

        {
            float sc[4][4];
#pragma unroll
            for (int i = 0; i < 4; i++)
#pragma unroll
                for (int j = 0; j < 4; j++) sc[i][j] = 0.f;
            for (int d = 0; d < 80; d++) {
                float qa[4], kb[4];
#pragma unroll
                for (int i = 0; i < 4; i++) qa[i] = Qs[(ty * 4 + i) * 80 + d];
#pragma unroll
                for (int j = 0; j < 4; j++) kb[j] = Ks[(j * 16 + tx) * 81 + d];
#pragma unroll
                for (int i = 0; i < 4; i++)
#pragma unroll
                    for (int j = 0; j < 4; j++) sc[i][j] = fmaf(qa[i], kb[j], sc[i][j]);
            }
#pragma unroll
            for (int i = 0; i < 4; i++)
#pragma unroll
                for (int j = 0; j < 4; j++)
                    Ss[(ty * 4 + i) * 65 + (j * 16 + tx)] = sc[i][j];
        }
        __syncthreads();

        {
            int r = tid >> 2, sub = tid & 3;
            float cmax = -1e30f;
            for (int c = sub * 16; c < sub * 16 + 16; c++)
                cmax = fmaxf(cmax, Ss[r * 65 + c]);
            cmax = fmaxf(cmax, __shfl_xor_sync(0xffffffffu, cmax, 1));
            cmax = fmaxf(cmax, __shfl_xor_sync(0xffffffffu, cmax, 2));
            float nm = fmaxf(mrow[r], cmax);
            float psum = 0.f;
            for (int c = sub * 16; c < sub * 16 + 16; c++) {
                float p = __expf(Ss[r * 65 + c] - nm);
                Ss[r * 65 + c] = p;
                psum += p;
            }
            psum += __shfl_xor_sync(0xffffffffu, psum, 1);
            psum += __shfl_xor_sync(0xffffffffu, psum, 2);
            if (sub == 0) {
                float cr = __expf(mrow[r] - nm);
                crow[r] = cr;
                lrow[r] = lrow[r] * cr + psum;
                mrow[r] = nm;
            }
        }
        __syncthreads();

#pragma unroll
        for (int i = 0; i < 4; i++) {
            float cr = crow[ty * 4 + i];
#pragma unroll
            for (int j = 0; j < 5; j++) acc[i][j] *= cr;
        }
        for (int k = 0; k < 64; k++) {
            float p[4], vv[5];
#pragma unroll
            for (int i = 0; i < 4; i++) p[i] = Ss[(ty * 4 + i) * 65 + k];
#pragma unroll
            for (int j = 0; j < 5; j++) vv[j] = Vs[k * 80 + tx * 5 + j];
#pragma unroll
            for (int i = 0; i < 4; i++)
#pragma unroll
                for (int j = 0; j < 5; j++) acc[i][j] = fmaf(p[i], vv[j], acc[i][j]);
        }
        __syncthreads();
    }

#pragma unroll
    for (int i = 0; i < 4; i++) {
        int q = ty * 4 + i;
        float inv = 1.f / lrow[q];
#pragma unroll
        for (int j = 0; j < 5; j++) {
            out[(size_t)(q0 + q) * DMODEL + head * HDIM + tx * 5 + j] = acc[i][j] * inv;
        }
    }
}

// ---------------------------------------------------------------------------
// Host side
// ---------------------------------------------------------------------------
static inline void run_gemm(int op, const float* A, int lda, const float* B, int ldb,
                            const float* bias, const float* resid,
                            float* C, int M, int N, int K)
{
    dim3 grid(N / 128, (M + 127) / 128);
    switch (op) {
        case 0: gemm_f16<0><<<grid, 256>>>(A, lda, B, ldb, bias, resid, C, M, N, K); break;
        case 1: gemm_f16<1><<<grid, 256>>>(A, lda, B, ldb, bias, resid, C, M, N, K); break;
        case 2: gemm_f16<2><<<grid, 256>>>(A, lda, B, ldb, bias, resid, C, M, N, K); break;
        case 3: gemm_f16<3><<<grid, 256>>>(A, lda, B, ldb, bias, resid, C, M, N, K); break;
    }
}

extern "C" void kernel_launch(void* const* d_in, const int* in_sizes, int n_in,
                              void* d_out, int out_size)
{
    const float* pixels  = (const float*)d_in[0];
    const float* rotary  = (const float*)d_in[1];
    const int*   seg_ids = (const int*)d_in[2];
    const float* proj_w  = (const float*)d_in[3];
    const float* ln1_w   = (const float*)d_in[4];
    const float* ln1_b   = (const float*)d_in[5];
    const float* qkv_w   = (const float*)d_in[6];
    const float* qkv_b   = (const float*)d_in[7];
    const float* po_w    = (const float*)d_in[8];
    const float* po_b    = (const float*)d_in[9];
    const float* ln2_w   = (const float*)d_in[10];
    const float* ln2_b   = (const float*)d_in[11];
    const float* fc1_w   = (const float*)d_in[12];
    const float* fc1_b   = (const float*)d_in[13];
    const float* fc2_w   = (const float*)d_in[14];
    const float* fc2_b   = (const float*)d_in[15];
    const float* mln_w   = (const float*)d_in[16];
    const float* mln_b   = (const float*)d_in[17];
    const float* m1_w    = (const float*)d_in[18];
    const float* m1_b    = (const float*)d_in[19];
    const float* m2_w    = (const float*)d_in[20];
    const float* m2_b    = (const float*)d_in[21];
    float* out = (float*)d_out;

    float *x, *ln, *qkv, *att, *big;
    cudaGetSymbolAddress((void**)&x,   g_x);
    cudaGetSymbolAddress((void**)&ln,  g_ln);
    cudaGetSymbolAddress((void**)&qkv, g_qkv);
    cudaGetSymbolAddress((void**)&att, g_att);
    cudaGetSymbolAddress((void**)&big, g_big);

    cudaFuncSetAttribute(attn_kernel, cudaFuncAttributeMaxDynamicSharedMemorySize,
                         ATT_SMEM_FLOATS * (int)sizeof(float));

    // patch projection: x = pixels @ proj_w^T (K=1176, no bias)
    run_gemm(0, pixels, 1176, proj_w, 1176, nullptr, nullptr, x, S_TOK, DMODEL, 1176);

    for (int l = 0; l < DEPTH; l++) {
        ln_kernel<<<S_TOK, 256>>>(x, ln1_w + l * DMODEL, ln1_b + l * DMODEL, ln);
        run_gemm(0, ln, DMODEL, qkv_w + (size_t)l * 3 * DMODEL * DMODEL, DMODEL,
                 qkv_b + (size_t)l * 3 * DMODEL, nullptr, qkv,
                 S_TOK, 3 * DMODEL, DMODEL);
        {
            int total = S_TOK * 2 * NHEAD * 40;
            rope_kernel<<<(total + 255) / 256, 256>>>(qkv, rotary);
        }
        {
            dim3 grid(NHEAD, S_TOK / 64);
            attn_kernel<<<grid, 256, ATT_SMEM_FLOATS * sizeof(float)>>>(qkv, seg_ids, att);
        }
        run_gemm(1, att, DMODEL, po_w + (size_t)l * DMODEL * DMODEL, DMODEL,
                 po_b + (size_t)l * DMODEL, x, x, S_TOK, DMODEL, DMODEL);
        ln_kernel<<<S_TOK, 256>>>(x, ln2_w + l * DMODEL, ln2_b + l * DMODEL, ln);
        run_gemm(2, ln, DMODEL, fc1_w + (size_t)l * 4 * DMODEL * DMODEL, DMODEL,
                 fc1_b + (size_t)l * 4 * DMODEL, nullptr, big,
                 S_TOK, 4 * DMODEL, DMODEL);
        run_gemm(1, big, 4 * DMODEL, fc2_w + (size_t)l * DMODEL * 4 * DMODEL, 4 * DMODEL,
                 fc2_b + (size_t)l * DMODEL, x, x, S_TOK, DMODEL, 4 * DMODEL);
    }

    ln_kernel<<<S_TOK, 256>>>(x, mln_w, mln_b, ln);
    // m1: (320,5120) @ (5120,5120)^T + GELU
    run_gemm(3, ln, 4 * DMODEL, m1_w, 4 * DMODEL, m1_b, nullptr, big,
             S_TOK / 4, 4 * DMODEL, 4 * DMODEL);
    // m2: split-K x4 -> partials in g_qkv, then reduce + bias
    {
        dim3 grid(1536 / 128, (320 + 127) / 128, 4);
        gemm_f16<4><<<grid, 256>>>(big, 4 * DMODEL, m2_w, 4 * DMODEL,
                                   nullptr, nullptr, qkv, 320, 1536, 4 * DMODEL / 4);
        reduce_m2<<<(320 * 1536 + 255) / 256, 256>>>(qkv, m2_b, out);
    }
}

// round 7
// speedup vs baseline: 4.1825x; 1.4326x over previous
#include <cuda_runtime.h>
#include <cuda_bf16.h>
#include <cuda_fp16.h>
#include <math.h>
#include <stdint.h>

// ---------------------------------------------------------------------------
// VisionModel: S=1280, D=1280, H=16, HD=80, DEPTH=4. Output (320,1536) fp32.
// GEMMs + attention on fp16 mma.sync (fp32 accum). LN/rope fp32.
// ---------------------------------------------------------------------------

#define S_TOK 1280
#define DMODEL 1280
#define NHEAD 16
#define HDIM 80
#define DEPTH 4

__device__ float g_x[S_TOK * DMODEL];
__device__ float g_ln[S_TOK * DMODEL];
__device__ float g_qkv[S_TOK * 3 * DMODEL];   // also m2 split-K partials
__device__ float g_att[S_TOK * DMODEL];
__device__ float g_big[S_TOK * 4 * DMODEL];
__device__ float g_part[4 * DMODEL * S_TOK];  // fc2 split-K partials

// ===========================================================================
// fp16 GEMM (as round 5): C = A@B^T + bias, OP 0 none/1 resid/2 SiLU/3 GELU/
// 4 split-K partial. BM=BN=128, BK=16, 256 thr, warp 32x64.
// ===========================================================================

__device__ __forceinline__ uint32_t pack_f16(float lo, float hi) {
    uint32_t r;
    asm("cvt.rn.f16x2.f32 %0, %1, %2;" : "=r"(r) : "f"(hi), "f"(lo));
    return r;
}

__device__ __forceinline__ void mma_f16(float* c,
    uint32_t a0, uint32_t a1, uint32_t a2, uint32_t a3,
    uint32_t b0, uint32_t b1)
{
    asm volatile(
        "mma.sync.aligned.m16n8k16.row.col.f32.f16.f16.f32 "
        "{%0,%1,%2,%3},{%4,%5,%6,%7},{%8,%9},{%0,%1,%2,%3};"
        : "+f"(c[0]), "+f"(c[1]), "+f"(c[2]), "+f"(c[3])
        : "r"(a0), "r"(a1), "r"(a2), "r"(a3), "r"(b0), "r"(b1));
}

template <int OP>
__device__ __forceinline__ float ep_op(float t, float r) {
    if (OP == 0 || OP == 4) return t;
    else if (OP == 1) return t + r;
    else if (OP == 2) return t / (1.f + __expf(-1.702f * t));
    else return 0.5f * t * (1.f + erff(t * 0.7071067811865475f));
}

__device__ __forceinline__ int swz(int r) { return ((r ^ (r >> 2)) & 3) << 1; }

template <int OP>
__global__ __launch_bounds__(256) void gemm_f16(
    const float* __restrict__ A, int lda,
    const float* __restrict__ B, int ldb,
    const float* __restrict__ bias, const float* __restrict__ resid,
    float* __restrict__ C, int M, int N, int K)
{
    __shared__ uint32_t As[2][128 * 8];
    __shared__ uint32_t Bs[2][128 * 8];

    if (OP == 4) {
        const size_t zo = (size_t)blockIdx.z * K;
        A += zo; B += zo;
        C += (size_t)blockIdx.z * (size_t)M * N;
    }

    const int tid  = threadIdx.x;
    const int warp = tid >> 5;
    const int lane = tid & 31;
    const int g = lane >> 2;
    const int t = lane & 3;

    const int m0 = blockIdx.y * 128;
    const int n0 = blockIdx.x * 128;
    const int warp_m = (warp & 3) * 32;
    const int warp_n = (warp >> 2) * 64;

    const int prow  = tid >> 1;
    const int khalf = tid & 1;
    const int pk8   = khalf * 8;
    const bool arow_ok = (m0 + prow) < M;
    const float* Ag = A + (size_t)(m0 + prow) * lda + pk8;
    const float* Bg = B + (size_t)(n0 + prow) * ldb + pk8;
    const int psw = swz(prow);
    int pcol[4];
#pragma unroll
    for (int j = 0; j < 4; j++) pcol[j] = prow * 8 + ((j * 2 + khalf) ^ psw);

    float acc[2][8][4];
#pragma unroll
    for (int am = 0; am < 2; am++)
#pragma unroll
        for (int bn = 0; bn < 8; bn++)
#pragma unroll
            for (int i = 0; i < 4; i++) acc[am][bn][i] = 0.f;

    const float4 z4 = make_float4(0.f, 0.f, 0.f, 0.f);
    float4 av0, av1, bv0, bv1;

    av0 = (arow_ok && pk8 < K)     ? *(const float4*)(Ag + 0) : z4;
    av1 = (arow_ok && pk8 + 4 < K) ? *(const float4*)(Ag + 4) : z4;
    bv0 = (pk8 < K)     ? *(const float4*)(Bg + 0) : z4;
    bv1 = (pk8 + 4 < K) ? *(const float4*)(Bg + 4) : z4;
    {
        const float a[8] = {av0.x, av0.y, av0.z, av0.w, av1.x, av1.y, av1.z, av1.w};
        const float b[8] = {bv0.x, bv0.y, bv0.z, bv0.w, bv1.x, bv1.y, bv1.z, bv1.w};
#pragma unroll
        for (int j = 0; j < 4; j++) {
            As[0][pcol[j]] = pack_f16(a[2 * j], a[2 * j + 1]);
            Bs[0][pcol[j]] = pack_f16(b[2 * j], b[2 * j + 1]);
        }
    }
    __syncthreads();

    int aoff[2][2], boff[8];
#pragma unroll
    for (int am = 0; am < 2; am++) {
        const int rl = warp_m + am * 16 + g;
        const int rh = rl + 8;
        aoff[am][0] = rl * 8 + ((2 * t) ^ swz(rl));
        aoff[am][1] = rh * 8 + ((2 * t) ^ swz(rh));
    }
#pragma unroll
    for (int bn = 0; bn < 8; bn++) {
        const int rn = warp_n + bn * 8 + g;
        boff[bn] = rn * 8 + ((2 * t) ^ swz(rn));
    }

    const int nstages = (K + 15) >> 4;
    int buf = 0;

    for (int s = 0; s < nstages; s++) {
        const bool has_next = (s + 1 < nstages);
        if (has_next) {
            const int k0 = (s + 1) << 4;
            av0 = (arow_ok && k0 + pk8 < K)     ? *(const float4*)(Ag + k0)     : z4;
            av1 = (arow_ok && k0 + pk8 + 4 < K) ? *(const float4*)(Ag + k0 + 4) : z4;
            bv0 = (k0 + pk8 < K)     ? *(const float4*)(Bg + k0)     : z4;
            bv1 = (k0 + pk8 + 4 < K) ? *(const float4*)(Bg + k0 + 4) : z4;
        }
        {
            const uint32_t* Ab = As[buf];
            const uint32_t* Bb = Bs[buf];
            uint2 afl[2], afh[2];
#pragma unroll
            for (int am = 0; am < 2; am++) {
                afl[am] = *(const uint2*)&Ab[aoff[am][0]];
                afh[am] = *(const uint2*)&Ab[aoff[am][1]];
            }
            uint2 bf[8];
#pragma unroll
            for (int bn = 0; bn < 8; bn++) bf[bn] = *(const uint2*)&Bb[boff[bn]];

#pragma unroll
            for (int am = 0; am < 2; am++)
#pragma unroll
                for (int bn = 0; bn < 8; bn++)
                    mma_f16(acc[am][bn],
                            afl[am].x, afh[am].x, afl[am].y, afh[am].y,
                            bf[bn].x, bf[bn].y);
        }
        if (has_next) {
            const float a[8] = {av0.x, av0.y, av0.z, av0.w, av1.x, av1.y, av1.z, av1.w};
            const float b[8] = {bv0.x, bv0.y, bv0.z, bv0.w, bv1.x, bv1.y, bv1.z, bv1.w};
            uint32_t* Ab = As[buf ^ 1];
            uint32_t* Bb = Bs[buf ^ 1];
#pragma unroll
            for (int j = 0; j < 4; j++) {
                Ab[pcol[j]] = pack_f16(a[2 * j], a[2 * j + 1]);
                Bb[pcol[j]] = pack_f16(b[2 * j], b[2 * j + 1]);
            }
        }
        __syncthreads();
        buf ^= 1;
    }

#pragma unroll
    for (int am = 0; am < 2; am++) {
        const int r0 = m0 + warp_m + am * 16 + g;
        const int r1 = r0 + 8;
#pragma unroll
        for (int bn = 0; bn < 8; bn++) {
            const int col = n0 + warp_n + bn * 8 + t * 2;
            const float2 bb = bias ? *(const float2*)&bias[col]
                                   : make_float2(0.f, 0.f);
            const float* cc = acc[am][bn];
            if (r0 < M) {
                float rx = 0.f, ry = 0.f;
                if (OP == 1) { const float2 rr = *(const float2*)&resid[(size_t)r0 * N + col]; rx = rr.x; ry = rr.y; }
                float2 o; o.x = ep_op<OP>(cc[0] + bb.x, rx); o.y = ep_op<OP>(cc[1] + bb.y, ry);
                *(float2*)&C[(size_t)r0 * N + col] = o;
            }
            if (r1 < M) {
                float rx = 0.f, ry = 0.f;
                if (OP == 1) { const float2 rr = *(const float2*)&resid[(size_t)r1 * N + col]; rx = rr.x; ry = rr.y; }
                float2 o; o.x = ep_op<OP>(cc[2] + bb.x, rx); o.y = ep_op<OP>(cc[3] + bb.y, ry);
                *(float2*)&C[(size_t)r1 * N + col] = o;
            }
        }
    }
}

// m2 split-K reduce: out[320,1536] = sum of 4 partials + bias
__global__ void reduce_m2(const float* __restrict__ part,
                          const float* __restrict__ bias,
                          float* __restrict__ out)
{
    const int i = blockIdx.x * 256 + threadIdx.x;
    const int total = 320 * 1536;
    if (i >= total) return;
    float s = bias[i % 1536];
#pragma unroll
    for (int c = 0; c < 4; c++) s += part[(size_t)c * total + i];
    out[i] = s;
}

// fc2 split-K reduce: x[1280,1280] += sum of 4 partials + bias
__global__ void reduce_fc2(const float* __restrict__ part,
                           const float* __restrict__ bias,
                           float* __restrict__ x)
{
    const int i = blockIdx.x * 256 + threadIdx.x;
    const int total = S_TOK * DMODEL;
    if (i >= total) return;
    float s = x[i] + bias[i % DMODEL];
#pragma unroll
    for (int c = 0; c < 4; c++) s += part[(size_t)c * total + i];
    x[i] = s;
}

// ---------------------------------------------------------------------------
// LayerNorm
// ---------------------------------------------------------------------------
__global__ __launch_bounds__(256) void ln_kernel(
    const float* __restrict__ x, const float* __restrict__ w,
    const float* __restrict__ b, float* __restrict__ y)
{
    const int row = blockIdx.x;
    const int tid = threadIdx.x;
    const float* xr = x + (size_t)row * DMODEL;

    float s = 0.f, sq = 0.f;
#pragma unroll
    for (int i = 0; i < DMODEL / 256; i++) {
        float v = xr[tid + i * 256];
        s += v; sq += v * v;
    }
#pragma unroll
    for (int o = 16; o > 0; o >>= 1) {
        s  += __shfl_xor_sync(0xffffffffu, s, o);
        sq += __shfl_xor_sync(0xffffffffu, sq, o);
    }
    __shared__ float ws[8], wsq[8];
    if ((tid & 31) == 0) { ws[tid >> 5] = s; wsq[tid >> 5] = sq; }
    __syncthreads();
    __shared__ float s_mu, s_rstd;
    if (tid == 0) {
        float ts = 0.f, tsq = 0.f;
        for (int i = 0; i < 8; i++) { ts += ws[i]; tsq += wsq[i]; }
        float mu = ts / DMODEL;
        float var = tsq / DMODEL - mu * mu;
        s_mu = mu;
        s_rstd = rsqrtf(var + 1e-6f);
    }
    __syncthreads();
    float mu = s_mu, rstd = s_rstd;
    float* yr = y + (size_t)row * DMODEL;
#pragma unroll
    for (int i = 0; i < DMODEL / 256; i++) {
        int c = tid + i * 256;
        yr[c] = (xr[c] - mu) * rstd * w[c] + b[c];
    }
}

// ---------------------------------------------------------------------------
// RoPE in place on q,k of g_qkv
// ---------------------------------------------------------------------------
__global__ void rope_kernel(float* __restrict__ qkv, const float* __restrict__ rotary)
{
    int i = blockIdx.x * blockDim.x + threadIdx.x;
    const int total = S_TOK * 2 * NHEAD * 40;
    if (i >= total) return;
    int d = i % 40;
    int h = (i / 40) % NHEAD;
    int part = (i / (40 * NHEAD)) % 2;
    int s = i / (40 * NHEAD * 2);

    int col = part * DMODEL + h * HDIM + d;
    float* base = qkv + (size_t)s * (3 * DMODEL);
    float x1 = base[col];
    float x2 = base[col + 40];
    float ang = rotary[s * 40 + d];
    float c, sn;
    sincosf(ang, &sn, &c);
    base[col]      = x1 * c - x2 * sn;
    base[col + 40] = x2 * c + x1 * sn;
}

// ===========================================================================
// Attention: FA2-style, fp16 mma (fp32 accum), 128 threads = 4 warps.
// Block = (head, 64 q-rows). Warp = 16 q-rows. K/V chunks of 64 keys.
// smem rows padded to 88 halves (176B) -> conflict-free ldmatrix.
// ===========================================================================
#define AT_STRIDE 88

__device__ __forceinline__ void ldsm4(uint32_t* r, uint32_t addr) {
    asm volatile("ldmatrix.sync.aligned.m8n8.x4.shared.b16 {%0,%1,%2,%3}, [%4];"
                 : "=r"(r[0]), "=r"(r[1]), "=r"(r[2]), "=r"(r[3]) : "r"(addr));
}
__device__ __forceinline__ void ldsm4t(uint32_t* r, uint32_t addr) {
    asm volatile("ldmatrix.sync.aligned.m8n8.x4.trans.shared.b16 {%0,%1,%2,%3}, [%4];"
                 : "=r"(r[0]), "=r"(r[1]), "=r"(r[2]), "=r"(r[3]) : "r"(addr));
}

__global__ __launch_bounds__(128) void attn_f16(
    const float* __restrict__ qkv, const int* __restrict__ seg,
    float* __restrict__ out)
{
    __shared__ __half Qs[64 * AT_STRIDE];
    __shared__ __half Ks[64 * AT_STRIDE];
    __shared__ __half Vs[64 * AT_STRIDE];

    const int head = blockIdx.x;
    const int q0   = blockIdx.y * 64;
    const int tid  = threadIdx.x;
    const int w    = tid >> 5;
    const int lane = tid & 31;
    const int g    = lane >> 2;
    const int t    = lane & 3;

    const float scale = 0.11180339887498949f; // 1/sqrt(80)

    uint32_t qb, kb, vb;
    asm("{ .reg .u64 u; cvta.to.shared.u64 u, %1; cvt.u32.u64 %0, u; }" : "=r"(qb) : "l"(Qs));
    asm("{ .reg .u64 u; cvta.to.shared.u64 u, %1; cvt.u32.u64 %0, u; }" : "=r"(kb) : "l"(Ks));
    asm("{ .reg .u64 u; cvta.to.shared.u64 u, %1; cvt.u32.u64 %0, u; }" : "=r"(vb) : "l"(Vs));

    // load Q (scaled) into smem fp16: row = tid>>1, half = tid&1 (40 floats)
    const int lrow = tid >> 1;
    const int lh   = tid & 1;
    {
        const float* src = qkv + (size_t)(q0 + lrow) * (3 * DMODEL) + head * HDIM + lh * 40;
        __half* dst = Qs + lrow * AT_STRIDE + lh * 40;
#pragma unroll
        for (int j = 0; j < 10; j++) {
            float4 v = *(const float4*)(src + j * 4);
            uint32_t p0 = pack_f16(v.x * scale, v.y * scale);
            uint32_t p1 = pack_f16(v.z * scale, v.w * scale);
            uint2 pp = make_uint2(p0, p1);
            *(uint2*)(dst + j * 4) = pp;
        }
    }

    float m[2] = {-1e30f, -1e30f};
    float l[2] = {0.f, 0.f};
    float oacc[10][4];
#pragma unroll
    for (int j = 0; j < 10; j++)
#pragma unroll
        for (int i = 0; i < 4; i++) oacc[j][i] = 0.f;

    const int myseg = seg[q0];

    // per-thread ldmatrix address components
    const uint32_t lrow16 = (uint32_t)(lane & 15);
    const uint32_t lhi16  = (uint32_t)(lane >> 4) * 16;
    const uint32_t q_addr0 = qb + (w * 16 + lrow16) * (AT_STRIDE * 2) + lhi16;

    __syncthreads();

    for (int c0 = 0; c0 < S_TOK; c0 += 64) {
        if (seg[c0] != myseg) continue;

        // load K,V chunk
        {
            const float* srcK = qkv + (size_t)(c0 + lrow) * (3 * DMODEL) + DMODEL + head * HDIM + lh * 40;
            const float* srcV = srcK + DMODEL;
            __half* dK = Ks + lrow * AT_STRIDE + lh * 40;
            __half* dV = Vs + lrow * AT_STRIDE + lh * 40;
#pragma unroll
            for (int j = 0; j < 10; j++) {
                float4 v = *(const float4*)(srcK + j * 4);
                *(uint2*)(dK + j * 4) = make_uint2(pack_f16(v.x, v.y), pack_f16(v.z, v.w));
                float4 u = *(const float4*)(srcV + j * 4);
                *(uint2*)(dV + j * 4) = make_uint2(pack_f16(u.x, u.y), pack_f16(u.z, u.w));
            }
        }
        __syncthreads();

        // scores: sacc[8 atoms][4]
        float sacc[8][4];
#pragma unroll
        for (int j = 0; j < 8; j++)
#pragma unroll
            for (int i = 0; i < 4; i++) sacc[j][i] = 0.f;

#pragma unroll
        for (int ks = 0; ks < 5; ks++) {
            uint32_t aq[4];
            ldsm4(aq, q_addr0 + ks * 32);
#pragma unroll
            for (int nb = 0; nb < 4; nb++) {
                uint32_t kr[4];
                ldsm4(kr, kb + (nb * 16 + lrow16) * (AT_STRIDE * 2) + lhi16 + ks * 32);
                mma_f16(sacc[2 * nb],     aq[0], aq[1], aq[2], aq[3], kr[0], kr[2]);
                mma_f16(sacc[2 * nb + 1], aq[0], aq[1], aq[2], aq[3], kr[1], kr[3]);
            }
        }

        // online softmax (registers only); rows g (i=0) and g+8 (i=1)
        float cs[2];
#pragma unroll
        for (int i = 0; i < 2; i++) {
            float cm = -1e30f;
#pragma unroll
            for (int j = 0; j < 8; j++) {
                cm = fmaxf(cm, sacc[j][2 * i]);
                cm = fmaxf(cm, sacc[j][2 * i + 1]);
            }
            cm = fmaxf(cm, __shfl_xor_sync(0xffffffffu, cm, 1));
            cm = fmaxf(cm, __shfl_xor_sync(0xffffffffu, cm, 2));
            const float nm = fmaxf(m[i], cm);
            cs[i] = __expf(m[i] - nm);
            m[i] = nm;
            float ps = 0.f;
#pragma unroll
            for (int j = 0; j < 8; j++) {
                float p0 = __expf(sacc[j][2 * i] - nm);
                float p1 = __expf(sacc[j][2 * i + 1] - nm);
                sacc[j][2 * i] = p0; sacc[j][2 * i + 1] = p1;
                ps += p0 + p1;
            }
            ps += __shfl_xor_sync(0xffffffffu, ps, 1);
            ps += __shfl_xor_sync(0xffffffffu, ps, 2);
            l[i] = l[i] * cs[i] + ps;
        }
#pragma unroll
        for (int j = 0; j < 10; j++) {
            oacc[j][0] *= cs[0]; oacc[j][1] *= cs[0];
            oacc[j][2] *= cs[1]; oacc[j][3] *= cs[1];
        }

        // PV: P fragments from sacc regs, V via ldmatrix.trans
#pragma unroll
        for (int ks = 0; ks < 4; ks++) {
            uint32_t pa[4];
            pa[0] = pack_f16(sacc[2 * ks][0],     sacc[2 * ks][1]);
            pa[1] = pack_f16(sacc[2 * ks][2],     sacc[2 * ks][3]);
            pa[2] = pack_f16(sacc[2 * ks + 1][0], sacc[2 * ks + 1][1]);
            pa[3] = pack_f16(sacc[2 * ks + 1][2], sacc[2 * ks + 1][3]);
#pragma unroll
            for (int db = 0; db < 5; db++) {
                uint32_t vr[4];
                ldsm4t(vr, vb + (ks * 16 + lrow16) * (AT_STRIDE * 2) + db * 32 + lhi16);
                mma_f16(oacc[2 * db],     pa[0], pa[1], pa[2], pa[3], vr[0], vr[1]);
                mma_f16(oacc[2 * db + 1], pa[0], pa[1], pa[2], pa[3], vr[2], vr[3]);
            }
        }
        __syncthreads();
    }

    // write out: rows q0 + w*16 + g (+8), cols head*80 + 8j + 2t
    const float inv0 = 1.f / l[0];
    const float inv1 = 1.f / l[1];
    const int r0 = q0 + w * 16 + g;
#pragma unroll
    for (int j = 0; j < 10; j++) {
        const int d = head * HDIM + j * 8 + t * 2;
        *(float2*)&out[(size_t)r0 * DMODEL + d] =
            make_float2(oacc[j][0] * inv0, oacc[j][1] * inv0);
        *(float2*)&out[(size_t)(r0 + 8) * DMODEL + d] =
            make_float2(oacc[j][2] * inv1, oacc[j][3] * inv1);
    }
}

// ---------------------------------------------------------------------------
// Host side
// ---------------------------------------------------------------------------
static inline void run_gemm(int op, const float* A, int lda, const float* B, int ldb,
                            const float* bias, const float* resid,
                            float* C, int M, int N, int K)
{
    dim3 grid(N / 128, (M + 127) / 128);
    switch (op) {
        case 0: gemm_f16<0><<<grid, 256>>>(A, lda, B, ldb, bias, resid, C, M, N, K); break;
        case 1: gemm_f16<1><<<grid, 256>>>(A, lda, B, ldb, bias, resid, C, M, N, K); break;
        case 2: gemm_f16<2><<<grid, 256>>>(A, lda, B, ldb, bias, resid, C, M, N, K); break;
        case 3: gemm_f16<3><<<grid, 256>>>(A, lda, B, ldb, bias, resid, C, M, N, K); break;
    }
}

extern "C" void kernel_launch(void* const* d_in, const int* in_sizes, int n_in,
                              void* d_out, int out_size)
{
    const float* pixels  = (const float*)d_in[0];
    const float* rotary  = (const float*)d_in[1];
    const int*   seg_ids = (const int*)d_in[2];
    const float* proj_w  = (const float*)d_in[3];
    const float* ln1_w   = (const float*)d_in[4];
    const float* ln1_b   = (const float*)d_in[5];
    const float* qkv_w   = (const float*)d_in[6];
    const float* qkv_b   = (const float*)d_in[7];
    const float* po_w    = (const float*)d_in[8];
    const float* po_b    = (const float*)d_in[9];
    const float* ln2_w   = (const float*)d_in[10];
    const float* ln2_b   = (const float*)d_in[11];
    const float* fc1_w   = (const float*)d_in[12];
    const float* fc1_b   = (const float*)d_in[13];
    const float* fc2_w   = (const float*)d_in[14];
    const float* fc2_b   = (const float*)d_in[15];
    const float* mln_w   = (const float*)d_in[16];
    const float* mln_b   = (const float*)d_in[17];
    const float* m1_w    = (const float*)d_in[18];
    const float* m1_b    = (const float*)d_in[19];
    const float* m2_w    = (const float*)d_in[20];
    const float* m2_b    = (const float*)d_in[21];
    float* out = (float*)d_out;

    float *x, *ln, *qkv, *att, *big, *part;
    cudaGetSymbolAddress((void**)&x,    g_x);
    cudaGetSymbolAddress((void**)&ln,   g_ln);
    cudaGetSymbolAddress((void**)&qkv,  g_qkv);
    cudaGetSymbolAddress((void**)&att,  g_att);
    cudaGetSymbolAddress((void**)&big,  g_big);
    cudaGetSymbolAddress((void**)&part, g_part);

    // patch projection: x = pixels @ proj_w^T (K=1176, no bias)
    run_gemm(0, pixels, 1176, proj_w, 1176, nullptr, nullptr, x, S_TOK, DMODEL, 1176);

    for (int l = 0; l < DEPTH; l++) {
        ln_kernel<<<S_TOK, 256>>>(x, ln1_w + l * DMODEL, ln1_b + l * DMODEL, ln);
        run_gemm(0, ln, DMODEL, qkv_w + (size_t)l * 3 * DMODEL * DMODEL, DMODEL,
                 qkv_b + (size_t)l * 3 * DMODEL, nullptr, qkv,
                 S_TOK, 3 * DMODEL, DMODEL);
        {
            int total = S_TOK * 2 * NHEAD * 40;
            rope_kernel<<<(total + 255) / 256, 256>>>(qkv, rotary);
        }
        {
            dim3 grid(NHEAD, S_TOK / 64);
            attn_f16<<<grid, 128>>>(qkv, seg_ids, att);
        }
        run_gemm(1, att, DMODEL, po_w + (size_t)l * DMODEL * DMODEL, DMODEL,
                 po_b + (size_t)l * DMODEL, x, x, S_TOK, DMODEL, DMODEL);
        ln_kernel<<<S_TOK, 256>>>(x, ln2_w + l * DMODEL, ln2_b + l * DMODEL, ln);
        run_gemm(2, ln, DMODEL, fc1_w + (size_t)l * 4 * DMODEL * DMODEL, DMODEL,
                 fc1_b + (size_t)l * 4 * DMODEL, nullptr, big,
                 S_TOK, 4 * DMODEL, DMODEL);
        // fc2: split-K x4 partials then fused reduce (+bias +residual into x)
        {
            dim3 grid(DMODEL / 128, S_TOK / 128, 4);
            gemm_f16<4><<<grid, 256>>>(big, 4 * DMODEL,
                                       fc2_w + (size_t)l * DMODEL * 4 * DMODEL, 4 * DMODEL,
                                       nullptr, nullptr, part, S_TOK, DMODEL, DMODEL);
            reduce_fc2<<<(S_TOK * DMODEL + 255) / 256, 256>>>(
                part, fc2_b + (size_t)l * DMODEL, x);
        }
    }

    ln_kernel<<<S_TOK, 256>>>(x, mln_w, mln_b, ln);
    run_gemm(3, ln, 4 * DMODEL, m1_w, 4 * DMODEL, m1_b, nullptr, big,
             S_TOK / 4, 4 * DMODEL, 4 * DMODEL);
    {
        dim3 grid(1536 / 128, (320 + 127) / 128, 4);
        gemm_f16<4><<<grid, 256>>>(big, 4 * DMODEL, m2_w, 4 * DMODEL,
                                   nullptr, nullptr, qkv, 320, 1536, 4 * DMODEL / 4);
        reduce_m2<<<(320 * 1536 + 255) / 256, 256>>>(qkv, m2_b, out);
    }
}